// round 14
// baseline (speedup 1.0000x reference)
#include <cuda_runtime.h>
#include <cuda_fp16.h>
#include <cstdint>

// OctonionLinear as dense fp16 mma.sync GEMM, fp32 accumulate.
//   Y[b, n] = sum_kk X[b, kk] * Bop(n, kk) + bias[n]
//   Bop(n=8i+c, kk) = W[i*32768 + kk*8 + c]
// R14: R13 kernels, but convert + GEMM split by K-half across TWO streams
// (event fork/join inside graph capture) so W-half-1 conversion overlaps the
// ks=0 GEMM. Both GEMM halves then run concurrently (full 256-CTA residency).

#define M_DIM 512
#define N_DIM 4096
#define K_DIM 4096
#define BM 128
#define BN 128
#define BK 64
#define NK (K_DIM / BK)            // 64
#define KSPLIT 2
#define NK_PER (NK / KSPLIT)       // 32
#define THREADS 256
#define STAGES 3

#define STRIDE_H 72                            // fp16 per row (144 B, conflict-free)
#define TILE_H (BM * STRIDE_H)                 // 9216 halves = 18432 B per tile
#define SMEM_BYTES (STAGES * 2 * TILE_H * 2)   // 110592 B

__device__ __align__(16) __half Wh_g[(size_t)N_DIM * K_DIM];  // 32 MB, [n][kk]
__device__ __align__(16) __half Xh_g[(size_t)M_DIM * K_DIM];  // 4 MB,  [b][kk]

// ------------- convert + zero kernel (part 0: W kk-half0 + X + zero Y;
//                                      part 1: W kk-half1) -------------
#define CONV_WBLOCKS_HALF 4096   // 512 octets x 8 kk-chunks of 256
#define CONV_XBLOCKS 2048
#define ZERO_BLOCKS  2048

__global__ __launch_bounds__(256)
void oct_convert(const float* __restrict__ W, const float* __restrict__ X,
                 float* __restrict__ Y, int part)
{
    const int t = threadIdx.x;
    const int b = blockIdx.x;
    if (b < CONV_WBLOCKS_HALF) {
        const int i = b >> 3;
        const int kk0 = ((b & 7) + part * 8) << 8;
        __shared__ __half sm[8][264];          // [c][kk]
        const float4* src = (const float4*)(W + (size_t)i * 32768 + (size_t)kk0 * 8);
        #pragma unroll
        for (int r = 0; r < 2; r++) {
            const int g = t + r * 256;         // float4 id: kk = g>>1, c0 = (g&1)*4
            float4 v = src[g];
            const int kk = g >> 1, c0 = (g & 1) * 4;
            sm[c0 + 0][kk] = __float2half_rn(v.x);
            sm[c0 + 1][kk] = __float2half_rn(v.y);
            sm[c0 + 2][kk] = __float2half_rn(v.z);
            sm[c0 + 3][kk] = __float2half_rn(v.w);
        }
        __syncthreads();
        const int c = t >> 5, j0 = (t & 31) * 8;
        uint4 out = *(const uint4*)&sm[c][j0];
        *(uint4*)(Wh_g + (size_t)(8 * i + c) * K_DIM + kk0 + j0) = out;
    } else if (b < CONV_WBLOCKS_HALF + CONV_XBLOCKS) {     // only present in part 0
        const size_t gid = (size_t)(b - CONV_WBLOCKS_HALF) * 1024 + (size_t)t * 4;
        float4 v = *(const float4*)(X + gid);
        __half2* dst = (__half2*)(Xh_g + gid);
        dst[0] = __floats2half2_rn(v.x, v.y);
        dst[1] = __floats2half2_rn(v.z, v.w);
    } else {
        const size_t gid = (size_t)(b - CONV_WBLOCKS_HALF - CONV_XBLOCKS) * 1024
                         + (size_t)t * 4;
        *(float4*)(Y + gid) = make_float4(0.f, 0.f, 0.f, 0.f);
    }
}

// ------------- GEMM kernel (one K-half per launch) -------------
__device__ __forceinline__ uint32_t smem_u32(const void* p) {
    uint32_t a;
    asm("{ .reg .u64 t; cvta.to.shared.u64 t, %1; cvt.u32.u64 %0, t; }" : "=r"(a) : "l"(p));
    return a;
}
__device__ __forceinline__ void cp16(uint32_t dst, const void* src) {
    asm volatile("cp.async.cg.shared.global [%0], [%1], 16;" :: "r"(dst), "l"(src));
}
#define CP_COMMIT() asm volatile("cp.async.commit_group;" ::: "memory")
#define CP_WAIT1()  asm volatile("cp.async.wait_group 1;" ::: "memory")
__device__ __forceinline__ void ldm4(uint32_t* r, uint32_t addr) {
    asm volatile("ldmatrix.sync.aligned.m8n8.x4.shared.b16 {%0,%1,%2,%3}, [%4];"
                 : "=r"(r[0]), "=r"(r[1]), "=r"(r[2]), "=r"(r[3]) : "r"(addr));
}
__device__ __forceinline__ void mma16(float* c, const uint32_t* a, const uint32_t* b) {
    asm volatile(
        "mma.sync.aligned.m16n8k16.row.col.f32.f16.f16.f32 "
        "{%0,%1,%2,%3}, {%4,%5,%6,%7}, {%8,%9}, {%0,%1,%2,%3};"
        : "+f"(c[0]), "+f"(c[1]), "+f"(c[2]), "+f"(c[3])
        : "r"(a[0]), "r"(a[1]), "r"(a[2]), "r"(a[3]), "r"(b[0]), "r"(b[1]));
}

__global__ __launch_bounds__(THREADS, 2)
void oct_mma_fp16_half(const float* __restrict__ Bias, float* __restrict__ Y, int kz)
{
    extern __shared__ __half hsm[];
    __half* Asm = hsm;
    __half* Bsm = hsm + STAGES * TILE_H;
    const uint32_t sAu = smem_u32(Asm);
    const uint32_t sBu = smem_u32(Bsm);

    const int t = threadIdx.x;
    const int w = t >> 5;
    const int l = t & 31;
    const int bm = blockIdx.y * BM;
    const int bn = blockIdx.x * BN;
    const int ks0 = kz * NK_PER;
    const int wm = (w & 3) * 32;
    const int wn = (w >> 2) * 64;
    const int wnOct = wn >> 3;

    const int lr = l >> 2;
    const int lc = l & 3;

    // ---- cp.async mapping: tile = 128 rows x 8 granules(16B); 4 per thread ----
    const int grow = t >> 3;
    const int gcol = t & 7;

    auto issue_cp = [&](int kt, int s) {
        const uint32_t aBase = sAu + (uint32_t)s * (TILE_H * 2);
        const uint32_t bBase = sBu + (uint32_t)s * (TILE_H * 2);
        const size_t kc0 = (size_t)kt * BK + gcol * 8;
        #pragma unroll
        for (int r = 0; r < 4; r++) {
            const int row = grow + r * 32;
            const uint32_t doff = (uint32_t)row * (STRIDE_H * 2) + (uint32_t)gcol * 16;
            cp16(aBase + doff, Xh_g + (size_t)(bm + row) * K_DIM + kc0);
            cp16(bBase + doff, Wh_g + (size_t)(bn + row) * K_DIM + kc0);
        }
    };

    // ---- ldmatrix lane addresses ----
    const int aRow = wm + (l & 7) + ((l >> 3) & 1) * 8;
    const uint32_t aOff0 = (uint32_t)(aRow * STRIDE_H + ((l >> 4) & 1) * 8) * 2;
    const uint32_t aOff1 = aOff0 + 16 * STRIDE_H * 2;
    const int bRow = (wnOct + ((l >> 4) & 1)) * 8 + (l & 7);
    const uint32_t bOff0 = (uint32_t)(bRow * STRIDE_H + ((l >> 3) & 1) * 8) * 2;

    // ---- acc init: split 0 carries bias, split 1 zero ----
    float acc[2][8][4];
    if (kz == 0) {
        #pragma unroll
        for (int j = 0; j < 8; j++) {
            const int n0 = bn + wn + j * 8 + lc * 2;
            const float b0v = Bias[n0];
            const float b1v = Bias[n0 + 1];
            #pragma unroll
            for (int mi = 0; mi < 2; mi++) {
                acc[mi][j][0] = b0v; acc[mi][j][1] = b1v;
                acc[mi][j][2] = b0v; acc[mi][j][3] = b1v;
            }
        }
    } else {
        #pragma unroll
        for (int mi = 0; mi < 2; mi++)
            #pragma unroll
            for (int j = 0; j < 8; j++)
                #pragma unroll
                for (int q = 0; q < 4; q++) acc[mi][j][q] = 0.0f;
    }

    // ---- prologue: stages 0,1 in flight ----
    issue_cp(ks0 + 0, 0); CP_COMMIT();
    issue_cp(ks0 + 1, 1); CP_COMMIT();
    CP_WAIT1();
    __syncthreads();

    for (int kt = 0; kt < NK_PER; kt++) {
        const int s = kt % STAGES;
        const uint32_t sAst = sAu + (uint32_t)s * (TILE_H * 2);
        const uint32_t sBst = sBu + (uint32_t)s * (TILE_H * 2);

        if (kt + 2 < NK_PER) issue_cp(ks0 + kt + 2, (kt + 2) % STAGES);
        CP_COMMIT();

        #pragma unroll
        for (int kc = 0; kc < 4; kc++) {
            const uint32_t kb = (uint32_t)kc * 32;
            uint32_t aF[2][4], bF[8][2];
            ldm4(aF[0], sAst + aOff0 + kb);
            ldm4(aF[1], sAst + aOff1 + kb);
            #pragma unroll
            for (int p = 0; p < 4; p++)
                ldm4(&bF[2 * p][0], sBst + bOff0 + (uint32_t)p * (16 * STRIDE_H * 2) + kb);
            #pragma unroll
            for (int mi = 0; mi < 2; mi++)
                #pragma unroll
                for (int j = 0; j < 8; j++)
                    mma16(acc[mi][j], aF[mi], bF[j]);
        }

        if (kt + 1 < NK_PER) {
            CP_WAIT1();
            __syncthreads();
        }
    }

    // ---- epilogue: atomicAdd partial sums into zeroed Y ----
    const int r0 = bm + wm + lr;
    #pragma unroll
    for (int mi = 0; mi < 2; mi++) {
        #pragma unroll
        for (int j = 0; j < 8; j++) {
            const int n0 = bn + wn + j * 8 + lc * 2;
            float* y0 = Y + (size_t)(r0 + mi * 16) * N_DIM + n0;
            float* y1 = Y + (size_t)(r0 + mi * 16 + 8) * N_DIM + n0;
            atomicAdd(y0,     acc[mi][j][0]);
            atomicAdd(y0 + 1, acc[mi][j][1]);
            atomicAdd(y1,     acc[mi][j][2]);
            atomicAdd(y1 + 1, acc[mi][j][3]);
        }
    }
}

extern "C" void kernel_launch(void* const* d_in, const int* in_sizes, int n_in,
                              void* d_out, int out_size)
{
    const float* x    = (const float*)d_in[0];  // [512, 4096]
    const float* wt   = (const float*)d_in[1];  // [512, 512, 8, 8]
    const float* bias = (const float*)d_in[2];  // [512, 8]
    float* y          = (float*)d_out;          // [512, 4096]

    static cudaStream_t s2 = nullptr;
    static cudaEvent_t evFork = nullptr, evJoin = nullptr;
    if (!s2) {
        cudaStreamCreateWithFlags(&s2, cudaStreamNonBlocking);
        cudaEventCreateWithFlags(&evFork, cudaEventDisableTiming);
        cudaEventCreateWithFlags(&evJoin, cudaEventDisableTiming);
    }

    cudaFuncSetAttribute(oct_mma_fp16_half,
                         cudaFuncAttributeMaxDynamicSharedMemorySize, SMEM_BYTES);
    dim3 grid(N_DIM / BN, M_DIM / BM);  // (32, 4) = 128 CTAs per half

    // main stream: convert W-half0 + X + zero-Y
    oct_convert<<<CONV_WBLOCKS_HALF + CONV_XBLOCKS + ZERO_BLOCKS, 256>>>(wt, x, y, 0);
    cudaEventRecord(evFork, 0);

    // side stream: convert W-half1, then GEMM ks=1 (joins residency with ks=0)
    cudaStreamWaitEvent(s2, evFork, 0);
    oct_convert<<<CONV_WBLOCKS_HALF, 256, 0, s2>>>(wt, x, y, 1);
    oct_mma_fp16_half<<<grid, THREADS, SMEM_BYTES, s2>>>(bias, y, 1);
    cudaEventRecord(evJoin, s2);

    // main stream: GEMM ks=0 runs concurrently with side-stream work
    oct_mma_fp16_half<<<grid, THREADS, SMEM_BYTES>>>(bias, y, 0);
    cudaStreamWaitEvent(0, evJoin, 0);
}

// round 15
// speedup vs baseline: 1.4774x; 1.4774x over previous
#include <cuda_runtime.h>
#include <cuda_fp16.h>
#include <cstdint>

// OctonionLinear as dense fp16 mma.sync GEMM, fp32 accumulate.
//   Y[b, n] = sum_kk X[b, kk] * Bop(n, kk) + bias[n]
//   Bop(n=8i+c, kk) = W[i*32768 + kk*8 + c]
// R15: R13 (BK=64, 3-stage cp.async, split-K(2), 2 CTAs/SM) + REGISTER-LEVEL
// fragment double-buffering across kc chunks: ldmatrix for kc+1 issues before
// the MMAs of kc, hiding LDS latency under tensor work.

#define M_DIM 512
#define N_DIM 4096
#define K_DIM 4096
#define BM 128
#define BN 128
#define BK 64
#define NK (K_DIM / BK)            // 64
#define KSPLIT 2
#define NK_PER (NK / KSPLIT)       // 32
#define THREADS 256
#define STAGES 3

#define STRIDE_H 72                            // fp16 per row (144 B, conflict-free)
#define TILE_H (BM * STRIDE_H)                 // 9216 halves = 18432 B per tile
#define SMEM_BYTES (STAGES * 2 * TILE_H * 2)   // 110592 B

__device__ __align__(16) __half Wh_g[(size_t)N_DIM * K_DIM];  // 32 MB, [n][kk]
__device__ __align__(16) __half Xh_g[(size_t)M_DIM * K_DIM];  // 4 MB,  [b][kk]

// ------------- convert + zero kernel -------------
#define CONV_WBLOCKS 8192   // 512 octets x 16 kk-chunks of 256
#define CONV_XBLOCKS 2048
#define ZERO_BLOCKS  2048

__global__ __launch_bounds__(256)
void oct_convert(const float* __restrict__ W, const float* __restrict__ X,
                 float* __restrict__ Y)
{
    const int t = threadIdx.x;
    const int b = blockIdx.x;
    if (b < CONV_WBLOCKS) {
        const int i = b >> 4;
        const int kk0 = (b & 15) << 8;
        __shared__ __half sm[8][264];          // [c][kk]
        const float4* src = (const float4*)(W + (size_t)i * 32768 + (size_t)kk0 * 8);
        #pragma unroll
        for (int r = 0; r < 2; r++) {
            const int g = t + r * 256;
            float4 v = src[g];
            const int kk = g >> 1, c0 = (g & 1) * 4;
            sm[c0 + 0][kk] = __float2half_rn(v.x);
            sm[c0 + 1][kk] = __float2half_rn(v.y);
            sm[c0 + 2][kk] = __float2half_rn(v.z);
            sm[c0 + 3][kk] = __float2half_rn(v.w);
        }
        __syncthreads();
        const int c = t >> 5, j0 = (t & 31) * 8;
        uint4 out = *(const uint4*)&sm[c][j0];
        *(uint4*)(Wh_g + (size_t)(8 * i + c) * K_DIM + kk0 + j0) = out;
    } else if (b < CONV_WBLOCKS + CONV_XBLOCKS) {
        const size_t gid = (size_t)(b - CONV_WBLOCKS) * 1024 + (size_t)t * 4;
        float4 v = *(const float4*)(X + gid);
        __half2* dst = (__half2*)(Xh_g + gid);
        dst[0] = __floats2half2_rn(v.x, v.y);
        dst[1] = __floats2half2_rn(v.z, v.w);
    } else {
        const size_t gid = (size_t)(b - CONV_WBLOCKS - CONV_XBLOCKS) * 1024
                         + (size_t)t * 4;
        *(float4*)(Y + gid) = make_float4(0.f, 0.f, 0.f, 0.f);
    }
}

// ------------- GEMM kernel -------------
__device__ __forceinline__ uint32_t smem_u32(const void* p) {
    uint32_t a;
    asm("{ .reg .u64 t; cvta.to.shared.u64 t, %1; cvt.u32.u64 %0, t; }" : "=r"(a) : "l"(p));
    return a;
}
__device__ __forceinline__ void cp16(uint32_t dst, const void* src) {
    asm volatile("cp.async.cg.shared.global [%0], [%1], 16;" :: "r"(dst), "l"(src));
}
#define CP_COMMIT() asm volatile("cp.async.commit_group;" ::: "memory")
#define CP_WAIT1()  asm volatile("cp.async.wait_group 1;" ::: "memory")
__device__ __forceinline__ void ldm4(uint32_t* r, uint32_t addr) {
    asm volatile("ldmatrix.sync.aligned.m8n8.x4.shared.b16 {%0,%1,%2,%3}, [%4];"
                 : "=r"(r[0]), "=r"(r[1]), "=r"(r[2]), "=r"(r[3]) : "r"(addr));
}
__device__ __forceinline__ void mma16(float* c, const uint32_t* a, const uint32_t* b) {
    asm volatile(
        "mma.sync.aligned.m16n8k16.row.col.f32.f16.f16.f32 "
        "{%0,%1,%2,%3}, {%4,%5,%6,%7}, {%8,%9}, {%0,%1,%2,%3};"
        : "+f"(c[0]), "+f"(c[1]), "+f"(c[2]), "+f"(c[3])
        : "r"(a[0]), "r"(a[1]), "r"(a[2]), "r"(a[3]), "r"(b[0]), "r"(b[1]));
}

__global__ __launch_bounds__(THREADS, 2)
void oct_mma_fp16_pipe(const float* __restrict__ Bias, float* __restrict__ Y)
{
    extern __shared__ __half hsm[];
    __half* Asm = hsm;
    __half* Bsm = hsm + STAGES * TILE_H;
    const uint32_t sAu = smem_u32(Asm);
    const uint32_t sBu = smem_u32(Bsm);

    const int t = threadIdx.x;
    const int w = t >> 5;
    const int l = t & 31;
    const int bm = blockIdx.y * BM;
    const int bn = blockIdx.x * BN;
    const int ks0 = blockIdx.z * NK_PER;
    const int wm = (w & 3) * 32;
    const int wn = (w >> 2) * 64;
    const int wnOct = wn >> 3;

    const int lr = l >> 2;
    const int lc = l & 3;

    // ---- cp.async mapping ----
    const int grow = t >> 3;
    const int gcol = t & 7;

    auto issue_cp = [&](int kt, int s) {
        const uint32_t aBase = sAu + (uint32_t)s * (TILE_H * 2);
        const uint32_t bBase = sBu + (uint32_t)s * (TILE_H * 2);
        const size_t kc0 = (size_t)kt * BK + gcol * 8;
        #pragma unroll
        for (int r = 0; r < 4; r++) {
            const int row = grow + r * 32;
            const uint32_t doff = (uint32_t)row * (STRIDE_H * 2) + (uint32_t)gcol * 16;
            cp16(aBase + doff, Xh_g + (size_t)(bm + row) * K_DIM + kc0);
            cp16(bBase + doff, Wh_g + (size_t)(bn + row) * K_DIM + kc0);
        }
    };

    // ---- ldmatrix lane addresses ----
    const int aRow = wm + (l & 7) + ((l >> 3) & 1) * 8;
    const uint32_t aOff0 = (uint32_t)(aRow * STRIDE_H + ((l >> 4) & 1) * 8) * 2;
    const uint32_t aOff1 = aOff0 + 16 * STRIDE_H * 2;
    const int bRow = (wnOct + ((l >> 4) & 1)) * 8 + (l & 7);
    const uint32_t bOff0 = (uint32_t)(bRow * STRIDE_H + ((l >> 3) & 1) * 8) * 2;

    // ---- acc init: split 0 carries bias, split 1 zero ----
    float acc[2][8][4];
    if (blockIdx.z == 0) {
        #pragma unroll
        for (int j = 0; j < 8; j++) {
            const int n0 = bn + wn + j * 8 + lc * 2;
            const float b0v = Bias[n0];
            const float b1v = Bias[n0 + 1];
            #pragma unroll
            for (int mi = 0; mi < 2; mi++) {
                acc[mi][j][0] = b0v; acc[mi][j][1] = b1v;
                acc[mi][j][2] = b0v; acc[mi][j][3] = b1v;
            }
        }
    } else {
        #pragma unroll
        for (int mi = 0; mi < 2; mi++)
            #pragma unroll
            for (int j = 0; j < 8; j++)
                #pragma unroll
                for (int q = 0; q < 4; q++) acc[mi][j][q] = 0.0f;
    }

    // ---- prologue: stages 0,1 in flight ----
    issue_cp(ks0 + 0, 0); CP_COMMIT();
    issue_cp(ks0 + 1, 1); CP_COMMIT();
    CP_WAIT1();
    __syncthreads();

    // fragment double buffers (ping-pong across kc)
    uint32_t aF[2][2][4], bF[2][8][2];

    auto load_frags = [&](uint32_t sAst, uint32_t sBst, int kc, int buf) {
        const uint32_t kb = (uint32_t)kc * 32;
        ldm4(aF[buf][0], sAst + aOff0 + kb);
        ldm4(aF[buf][1], sAst + aOff1 + kb);
        #pragma unroll
        for (int p = 0; p < 4; p++)
            ldm4(&bF[buf][2 * p][0], sBst + bOff0 + (uint32_t)p * (16 * STRIDE_H * 2) + kb);
    };

    for (int kt = 0; kt < NK_PER; kt++) {
        const int s = kt % STAGES;
        const uint32_t sAst = sAu + (uint32_t)s * (TILE_H * 2);
        const uint32_t sBst = sBu + (uint32_t)s * (TILE_H * 2);

        if (kt + 2 < NK_PER) issue_cp(ks0 + kt + 2, (kt + 2) % STAGES);
        CP_COMMIT();

        load_frags(sAst, sBst, 0, 0);   // kc=0 into buf 0

        #pragma unroll
        for (int kc = 0; kc < 4; kc++) {
            const int cur = kc & 1;
            if (kc < 3) load_frags(sAst, sBst, kc + 1, cur ^ 1);  // prefetch next
            #pragma unroll
            for (int mi = 0; mi < 2; mi++)
                #pragma unroll
                for (int j = 0; j < 8; j++)
                    mma16(acc[mi][j], aF[cur][mi], bF[cur][j]);
        }

        if (kt + 1 < NK_PER) {
            CP_WAIT1();
            __syncthreads();
        }
    }

    // ---- epilogue: atomicAdd partial sums into zeroed Y ----
    const int r0 = bm + wm + lr;
    #pragma unroll
    for (int mi = 0; mi < 2; mi++) {
        #pragma unroll
        for (int j = 0; j < 8; j++) {
            const int n0 = bn + wn + j * 8 + lc * 2;
            float* y0 = Y + (size_t)(r0 + mi * 16) * N_DIM + n0;
            float* y1 = Y + (size_t)(r0 + mi * 16 + 8) * N_DIM + n0;
            atomicAdd(y0,     acc[mi][j][0]);
            atomicAdd(y0 + 1, acc[mi][j][1]);
            atomicAdd(y1,     acc[mi][j][2]);
            atomicAdd(y1 + 1, acc[mi][j][3]);
        }
    }
}

extern "C" void kernel_launch(void* const* d_in, const int* in_sizes, int n_in,
                              void* d_out, int out_size)
{
    const float* x    = (const float*)d_in[0];  // [512, 4096]
    const float* wt   = (const float*)d_in[1];  // [512, 512, 8, 8]
    const float* bias = (const float*)d_in[2];  // [512, 8]
    float* y          = (float*)d_out;          // [512, 4096]

    oct_convert<<<CONV_WBLOCKS + CONV_XBLOCKS + ZERO_BLOCKS, 256>>>(wt, x, y);

    cudaFuncSetAttribute(oct_mma_fp16_pipe, cudaFuncAttributeMaxDynamicSharedMemorySize, SMEM_BYTES);
    dim3 grid(N_DIM / BN, M_DIM / BM, KSPLIT);  // (32, 4, 2) = 256 CTAs
    oct_mma_fp16_pipe<<<grid, THREADS, SMEM_BYTES>>>(bias, y);
}

// round 16
// speedup vs baseline: 1.6019x; 1.0843x over previous
#include <cuda_runtime.h>
#include <cuda_fp16.h>
#include <cstdint>

// OctonionLinear as dense fp16 mma.sync GEMM, fp32 accumulate.
//   Y[b, n] = sum_kk X[b, kk] * Bop(n, kk) + bias[n]
//   Bop(n=8i+c, kk) = W[i*32768 + kk*8 + c]
// R16: R13 engine + BALANCED 296-CTA schedule (148 SMs x occ 2, zero wave
// quantization): 8192 kt-units split 200x28 + 96x27 across CTAs; each CTA
// runs 1-2 tile-segments with per-segment pipeline restart + atomic epilogue.

#define M_DIM 512
#define N_DIM 4096
#define K_DIM 4096
#define BM 128
#define BN 128
#define BK 64
#define NKT 64                     // kt-units per tile
#define NTILES 128                 // 4 M x 32 N
#define TOTAL_U (NTILES * NKT)     // 8192
#define NCTAS 296
#define THREADS 256
#define STAGES 3

#define STRIDE_H 72                            // fp16 per row (144 B, conflict-free)
#define TILE_H (BM * STRIDE_H)                 // 9216 halves = 18432 B per tile
#define SMEM_BYTES (STAGES * 2 * TILE_H * 2)   // 110592 B

__device__ __align__(16) __half Wh_g[(size_t)N_DIM * K_DIM];  // 32 MB, [n][kk]
__device__ __align__(16) __half Xh_g[(size_t)M_DIM * K_DIM];  // 4 MB,  [b][kk]

// ------------- convert + zero kernel -------------
#define CONV_WBLOCKS 8192
#define CONV_XBLOCKS 2048
#define ZERO_BLOCKS  2048

__global__ __launch_bounds__(256)
void oct_convert(const float* __restrict__ W, const float* __restrict__ X,
                 float* __restrict__ Y)
{
    const int t = threadIdx.x;
    const int b = blockIdx.x;
    if (b < CONV_WBLOCKS) {
        const int i = b >> 4;
        const int kk0 = (b & 15) << 8;
        __shared__ __half sm[8][264];
        const float4* src = (const float4*)(W + (size_t)i * 32768 + (size_t)kk0 * 8);
        #pragma unroll
        for (int r = 0; r < 2; r++) {
            const int g = t + r * 256;
            float4 v = src[g];
            const int kk = g >> 1, c0 = (g & 1) * 4;
            sm[c0 + 0][kk] = __float2half_rn(v.x);
            sm[c0 + 1][kk] = __float2half_rn(v.y);
            sm[c0 + 2][kk] = __float2half_rn(v.z);
            sm[c0 + 3][kk] = __float2half_rn(v.w);
        }
        __syncthreads();
        const int c = t >> 5, j0 = (t & 31) * 8;
        uint4 out = *(const uint4*)&sm[c][j0];
        *(uint4*)(Wh_g + (size_t)(8 * i + c) * K_DIM + kk0 + j0) = out;
    } else if (b < CONV_WBLOCKS + CONV_XBLOCKS) {
        const size_t gid = (size_t)(b - CONV_WBLOCKS) * 1024 + (size_t)t * 4;
        float4 v = *(const float4*)(X + gid);
        __half2* dst = (__half2*)(Xh_g + gid);
        dst[0] = __floats2half2_rn(v.x, v.y);
        dst[1] = __floats2half2_rn(v.z, v.w);
    } else {
        const size_t gid = (size_t)(b - CONV_WBLOCKS - CONV_XBLOCKS) * 1024
                         + (size_t)t * 4;
        *(float4*)(Y + gid) = make_float4(0.f, 0.f, 0.f, 0.f);
    }
}

// ------------- GEMM kernel -------------
__device__ __forceinline__ uint32_t smem_u32(const void* p) {
    uint32_t a;
    asm("{ .reg .u64 t; cvta.to.shared.u64 t, %1; cvt.u32.u64 %0, t; }" : "=r"(a) : "l"(p));
    return a;
}
__device__ __forceinline__ void cp16(uint32_t dst, const void* src) {
    asm volatile("cp.async.cg.shared.global [%0], [%1], 16;" :: "r"(dst), "l"(src));
}
#define CP_COMMIT() asm volatile("cp.async.commit_group;" ::: "memory")
#define CP_WAIT1()  asm volatile("cp.async.wait_group 1;" ::: "memory")
__device__ __forceinline__ void ldm4(uint32_t* r, uint32_t addr) {
    asm volatile("ldmatrix.sync.aligned.m8n8.x4.shared.b16 {%0,%1,%2,%3}, [%4];"
                 : "=r"(r[0]), "=r"(r[1]), "=r"(r[2]), "=r"(r[3]) : "r"(addr));
}
__device__ __forceinline__ void mma16(float* c, const uint32_t* a, const uint32_t* b) {
    asm volatile(
        "mma.sync.aligned.m16n8k16.row.col.f32.f16.f16.f32 "
        "{%0,%1,%2,%3}, {%4,%5,%6,%7}, {%8,%9}, {%0,%1,%2,%3};"
        : "+f"(c[0]), "+f"(c[1]), "+f"(c[2]), "+f"(c[3])
        : "r"(a[0]), "r"(a[1]), "r"(a[2]), "r"(a[3]), "r"(b[0]), "r"(b[1]));
}

__global__ __launch_bounds__(THREADS, 2)
void oct_mma_fp16_bal(const float* __restrict__ Bias, float* __restrict__ Y)
{
    extern __shared__ __half hsm[];
    __half* Asm = hsm;
    __half* Bsm = hsm + STAGES * TILE_H;
    const uint32_t sAu = smem_u32(Asm);
    const uint32_t sBu = smem_u32(Bsm);

    const int t = threadIdx.x;
    const int w = t >> 5;
    const int l = t & 31;
    const int wm = (w & 3) * 32;
    const int wn = (w >> 2) * 64;
    const int wnOct = wn >> 3;
    const int lr = l >> 2;
    const int lc = l & 3;

    // ---- balanced schedule: CTA p owns kt-units [start, start+quota) ----
    const int p = blockIdx.x;
    const int over = (p > 200) ? (p - 200) : 0;
    int u   = p * 28 - over;
    int rem = (p < 200) ? 28 : 27;

    // ---- cp.async mapping ----
    const int grow = t >> 3;
    const int gcol = t & 7;

    // ---- ldmatrix lane addresses (bytes from stage base) ----
    const int aRow = wm + (l & 7) + ((l >> 3) & 1) * 8;
    const uint32_t aOff0 = (uint32_t)(aRow * STRIDE_H + ((l >> 4) & 1) * 8) * 2;
    const uint32_t aOff1 = aOff0 + 16 * STRIDE_H * 2;
    const int bRow = (wnOct + ((l >> 4) & 1)) * 8 + (l & 7);
    const uint32_t bOff0 = (uint32_t)(bRow * STRIDE_H + ((l >> 3) & 1) * 8) * 2;

    while (rem > 0) {
        const int tl  = u >> 6;            // tile index
        const int k0  = u & 63;            // first kt in this tile
        const int len = min(NKT - k0, rem);
        const int bm  = (tl >> 5) * BM;
        const int bn  = (tl & 31) * BN;

        auto issue_cp = [&](int kt, int s) {
            const uint32_t aBase = sAu + (uint32_t)s * (TILE_H * 2);
            const uint32_t bBase = sBu + (uint32_t)s * (TILE_H * 2);
            const size_t kc0 = (size_t)kt * BK + gcol * 8;
            #pragma unroll
            for (int r = 0; r < 4; r++) {
                const int row = grow + r * 32;
                const uint32_t doff = (uint32_t)row * (STRIDE_H * 2) + (uint32_t)gcol * 16;
                cp16(aBase + doff, Xh_g + (size_t)(bm + row) * K_DIM + kc0);
                cp16(bBase + doff, Wh_g + (size_t)(bn + row) * K_DIM + kc0);
            }
        };

        // ---- acc init: the segment owning kt==0 carries the bias ----
        float acc[2][8][4];
        if (k0 == 0) {
            #pragma unroll
            for (int j = 0; j < 8; j++) {
                const int n0 = bn + wn + j * 8 + lc * 2;
                const float b0v = Bias[n0];
                const float b1v = Bias[n0 + 1];
                #pragma unroll
                for (int mi = 0; mi < 2; mi++) {
                    acc[mi][j][0] = b0v; acc[mi][j][1] = b1v;
                    acc[mi][j][2] = b0v; acc[mi][j][3] = b1v;
                }
            }
        } else {
            #pragma unroll
            for (int mi = 0; mi < 2; mi++)
                #pragma unroll
                for (int j = 0; j < 8; j++)
                    #pragma unroll
                    for (int q = 0; q < 4; q++) acc[mi][j][q] = 0.0f;
        }

        // ---- prologue ----
        issue_cp(k0 + 0, 0); CP_COMMIT();
        if (len > 1) issue_cp(k0 + 1, 1);
        CP_COMMIT();
        CP_WAIT1();
        __syncthreads();

        for (int j2 = 0; j2 < len; j2++) {
            const int s = j2 % STAGES;
            const uint32_t sAst = sAu + (uint32_t)s * (TILE_H * 2);
            const uint32_t sBst = sBu + (uint32_t)s * (TILE_H * 2);

            if (j2 + 2 < len) issue_cp(k0 + j2 + 2, (j2 + 2) % STAGES);
            CP_COMMIT();

            #pragma unroll
            for (int kc = 0; kc < 4; kc++) {
                const uint32_t kb = (uint32_t)kc * 32;
                uint32_t aF[2][4], bF[8][2];
                ldm4(aF[0], sAst + aOff0 + kb);
                ldm4(aF[1], sAst + aOff1 + kb);
                #pragma unroll
                for (int pq = 0; pq < 4; pq++)
                    ldm4(&bF[2 * pq][0], sBst + bOff0 + (uint32_t)pq * (16 * STRIDE_H * 2) + kb);
                #pragma unroll
                for (int mi = 0; mi < 2; mi++)
                    #pragma unroll
                    for (int j = 0; j < 8; j++)
                        mma16(acc[mi][j], aF[mi], bF[j]);
            }

            if (j2 + 1 < len) {
                CP_WAIT1();
                __syncthreads();
            }
        }

        // ---- epilogue: atomicAdd partial sums ----
        const int r0 = bm + wm + lr;
        #pragma unroll
        for (int mi = 0; mi < 2; mi++) {
            #pragma unroll
            for (int j = 0; j < 8; j++) {
                const int n0 = bn + wn + j * 8 + lc * 2;
                float* y0 = Y + (size_t)(r0 + mi * 16) * N_DIM + n0;
                float* y1 = Y + (size_t)(r0 + mi * 16 + 8) * N_DIM + n0;
                atomicAdd(y0,     acc[mi][j][0]);
                atomicAdd(y0 + 1, acc[mi][j][1]);
                atomicAdd(y1,     acc[mi][j][2]);
                atomicAdd(y1 + 1, acc[mi][j][3]);
            }
        }

        u   += len;
        rem -= len;
        if (rem > 0) __syncthreads();   // all warps done with smem before refill
    }
}

extern "C" void kernel_launch(void* const* d_in, const int* in_sizes, int n_in,
                              void* d_out, int out_size)
{
    const float* x    = (const float*)d_in[0];  // [512, 4096]
    const float* wt   = (const float*)d_in[1];  // [512, 512, 8, 8]
    const float* bias = (const float*)d_in[2];  // [512, 8]
    float* y          = (float*)d_out;          // [512, 4096]

    oct_convert<<<CONV_WBLOCKS + CONV_XBLOCKS + ZERO_BLOCKS, 256>>>(wt, x, y);

    cudaFuncSetAttribute(oct_mma_fp16_bal, cudaFuncAttributeMaxDynamicSharedMemorySize, SMEM_BYTES);
    oct_mma_fp16_bal<<<NCTAS, THREADS, SMEM_BYTES>>>(bias, y);
}